// round 2
// baseline (speedup 1.0000x reference)
#include <cuda_runtime.h>

#define BATCH 64
#define TT    200
#define NUM_C 2000
#define DIM   128
#define MM    50
#define MP    56          // M padded; rows 50..55 have w=0 (inert)
#define NX    4000        // distinct x = skill + 2000*answer

// ---------------- scratch (device globals; no allocation allowed) ----------
__device__ __align__(16) float g_w[NUM_C * MP];       // softmax(k·Mk^T) per skill id
__device__ __align__(16) float g_ea[NX * 256];        // [x][0:128]=e, [128:256]=a
__device__ __align__(16) float g_kf[NUM_C * DIM];     // k-part of f GEMM + f_b folded
__device__ __align__(16) float g_reads[BATCH * TT * DIM];
__device__ __align__(16) float g_fWat[DIM * DIM];     // [k][i] = f_W[i*256 + k] (reads part)

__device__ __forceinline__ float sigmoidf_(float x) { return 1.f / (1.f + __expf(-x)); }

// =====================================================================
// Fused tables kernel: one launch, 321 CTAs, role by blockIdx.
//   bid [0,125)    : e/a table   (32 x-rows per CTA)
//   bid [125,250)  : w table     (16 skills per CTA)
//   bid [250,313)  : kf table    (32 skills per CTA)
//   bid [313,321)  : f_W (reads half) transpose into g_fWat
// Weight transposes are folded into the smem tile loads (padded pitches
// avoid bank conflicts). ~35KB smem/CTA -> ~6 CTAs/SM.
// =====================================================================
__global__ void k_tables(const float* __restrict__ k_emb, const float* __restrict__ Mk,
                         const float* __restrict__ v_emb,
                         const float* __restrict__ e_b, const float* __restrict__ a_b,
                         const float* __restrict__ f_W, const float* __restrict__ f_b,
                         const float* __restrict__ e_W, const float* __restrict__ a_W) {
    __shared__ __align__(16) float sm[8960];
    int bid = blockIdx.x;
    int tid = threadIdx.x;

    if (bid < 125) {
        // ---------------- e/a table GEMM: rows of v_emb x [e_W^T | a_W^T] ----
        float* Xs = sm;                 // [32][128]
        float* Ws = sm + 4096;          // [16][260] (pitch 260, 16B-aligned rows)
        int row0 = bid * 32;
        for (int i = tid; i < 32 * DIM; i += 256) Xs[i] = v_emb[row0 * DIM + i];
        int tx = tid & 31, ty = tid >> 5;       // col = tx*8, rows ty*4..+3
        float acc[4][8];
        #pragma unroll
        for (int u = 0; u < 4; u++)
            #pragma unroll
            for (int v = 0; v < 8; v++) acc[u][v] = 0.f;
        for (int kc = 0; kc < DIM; kc += 16) {
            __syncthreads();
            for (int i = tid; i < 16 * 256; i += 256) {
                int kk = i & 15, c = i >> 4;    // coalesced read, transposed write
                float v = (c < DIM) ? e_W[c * DIM + kc + kk] : a_W[(c - DIM) * DIM + kc + kk];
                Ws[kk * 260 + c] = v;
            }
            __syncthreads();
            #pragma unroll
            for (int kk = 0; kk < 16; kk++) {
                float xv[4];
                #pragma unroll
                for (int u = 0; u < 4; u++) xv[u] = Xs[(ty * 4 + u) * DIM + kc + kk];
                float4 w0 = *(const float4*)&Ws[kk * 260 + tx * 8];
                float4 w1 = *(const float4*)&Ws[kk * 260 + tx * 8 + 4];
                #pragma unroll
                for (int u = 0; u < 4; u++) {
                    acc[u][0] = fmaf(xv[u], w0.x, acc[u][0]);
                    acc[u][1] = fmaf(xv[u], w0.y, acc[u][1]);
                    acc[u][2] = fmaf(xv[u], w0.z, acc[u][2]);
                    acc[u][3] = fmaf(xv[u], w0.w, acc[u][3]);
                    acc[u][4] = fmaf(xv[u], w1.x, acc[u][4]);
                    acc[u][5] = fmaf(xv[u], w1.y, acc[u][5]);
                    acc[u][6] = fmaf(xv[u], w1.z, acc[u][6]);
                    acc[u][7] = fmaf(xv[u], w1.w, acc[u][7]);
                }
            }
        }
        int col = tx * 8;
        float barr[8];
        #pragma unroll
        for (int v = 0; v < 8; v++) {
            int cc = col + v;
            barr[v] = (cc < DIM) ? e_b[cc] : a_b[cc - DIM];
        }
        #pragma unroll
        for (int u = 0; u < 4; u++) {
            float o[8];
            #pragma unroll
            for (int v = 0; v < 8; v++) {
                float z = acc[u][v] + barr[v];
                o[v] = (col + v < DIM) ? sigmoidf_(z) : tanhf(z);
            }
            int r = row0 + ty * 4 + u;
            *(float4*)&g_ea[r * 256 + col]     = make_float4(o[0], o[1], o[2], o[3]);
            *(float4*)&g_ea[r * 256 + col + 4] = make_float4(o[4], o[5], o[6], o[7]);
        }
    } else if (bid < 250) {
        // ---------------- w table: softmax(k_emb[c] · Mk^T) ------------------
        float* mksh = sm;               // [128][65] padded (conflict-free T write)
        float* ksh  = sm + 8320;        // [4][128]
        float* gmax = sm + 8832;        // [4][2]
        float* gsum = sm + 8840;        // [4][2]
        int c0 = (bid - 125) * 16;
        int m = tid & 63, cg = tid >> 6, wh = (tid >> 5) & 1;
        for (int i = tid; i < MM * DIM; i += 256) {
            int mm = i >> 7, j = i & 127;
            mksh[j * 65 + mm] = Mk[i];
        }
        for (int cl = 0; cl < 16; cl += 4) {
            int c = c0 + cl + cg;
            __syncthreads();
            for (int j = tid; j < 4 * DIM; j += 256)
                ksh[j] = k_emb[(c0 + cl + (j >> 7)) * DIM + (j & 127)];
            __syncthreads();
            float acc = 0.f;
            if (m < MM) {
                #pragma unroll 8
                for (int j = 0; j < DIM; j++) acc = fmaf(ksh[cg * DIM + j], mksh[j * 65 + m], acc);
            }
            float lg = (m < MM) ? acc : -1e30f;
            float mx = lg;
            #pragma unroll
            for (int off = 16; off; off >>= 1) mx = fmaxf(mx, __shfl_xor_sync(~0u, mx, off));
            if ((tid & 31) == 0) gmax[cg * 2 + wh] = mx;
            __syncthreads();
            mx = fmaxf(gmax[cg * 2], gmax[cg * 2 + 1]);
            float ex = (m < MM) ? __expf(lg - mx) : 0.f;
            float sv = ex;
            #pragma unroll
            for (int off = 16; off; off >>= 1) sv += __shfl_xor_sync(~0u, sv, off);
            if ((tid & 31) == 0) gsum[cg * 2 + wh] = sv;
            __syncthreads();
            float s = gsum[cg * 2] + gsum[cg * 2 + 1];
            if (m < MP) g_w[c * MP + m] = ex / s;
        }
    } else if (bid < 313) {
        // ---------------- kf table: k_emb @ fWb^T + f_b -----------------------
        float* Xs = sm;                 // [32][128]
        float* Ws = sm + 4096;          // [16][132]
        int row0 = (bid - 250) * 32;
        for (int i = tid; i < 32 * DIM; i += 256) {
            int rr = i >> 7;
            Xs[i] = (row0 + rr < NUM_C) ? k_emb[row0 * DIM + i] : 0.f;
        }
        int tx = tid & 31, ty = tid >> 5;      // col = tx*4
        float acc[4][4];
        #pragma unroll
        for (int u = 0; u < 4; u++)
            #pragma unroll
            for (int v = 0; v < 4; v++) acc[u][v] = 0.f;
        for (int kc = 0; kc < DIM; kc += 16) {
            __syncthreads();
            for (int i = tid; i < 16 * DIM; i += 256) {
                int kk = i & 15, col = i >> 4;
                Ws[kk * 132 + col] = f_W[col * 256 + 128 + kc + kk];
            }
            __syncthreads();
            #pragma unroll
            for (int kk = 0; kk < 16; kk++) {
                float xv[4];
                #pragma unroll
                for (int u = 0; u < 4; u++) xv[u] = Xs[(ty * 4 + u) * DIM + kc + kk];
                float4 w0 = *(const float4*)&Ws[kk * 132 + tx * 4];
                #pragma unroll
                for (int u = 0; u < 4; u++) {
                    acc[u][0] = fmaf(xv[u], w0.x, acc[u][0]);
                    acc[u][1] = fmaf(xv[u], w0.y, acc[u][1]);
                    acc[u][2] = fmaf(xv[u], w0.z, acc[u][2]);
                    acc[u][3] = fmaf(xv[u], w0.w, acc[u][3]);
                }
            }
        }
        int col = tx * 4;
        float b0 = f_b[col], b1 = f_b[col + 1], b2 = f_b[col + 2], b3 = f_b[col + 3];
        #pragma unroll
        for (int u = 0; u < 4; u++) {
            int r = row0 + ty * 4 + u;
            if (r < NUM_C)
                *(float4*)&g_kf[r * DIM + col] =
                    make_float4(acc[u][0] + b0, acc[u][1] + b1, acc[u][2] + b2, acc[u][3] + b3);
        }
    } else {
        // ---------------- g_fWat[k][i] = f_W[i*256 + k] ----------------------
        int base = (bid - 313) * 2048;
        #pragma unroll
        for (int j = 0; j < 8; j++) {
            int idx = base + j * 256 + tid;
            int k = idx >> 7, ii = idx & 127;
            g_fWat[idx] = f_W[ii * 256 + k];
        }
    }
}

// =====================================================================
// Sequential scan: 128 CTAs = 64 batches x 2 d-halves, 256 threads.
// ONE __syncthreads per step; depth-3 prefetch pipeline (LDG@t ->
// reg -> STS@t+2 -> consume@t+3); g_reads reduction deferred one step
// (off the recurrence critical path) via double-buffered red.
// =====================================================================
__global__ void k_scan(const int* __restrict__ skill, const int* __restrict__ answer,
                       const float* __restrict__ Mv0) {
    __shared__ int s_sk[TT], s_x[TT];
    __shared__ __align__(16) float w_sh[4][MP];
    __shared__ __align__(16) float e_sh[4][64];
    __shared__ __align__(16) float a_sh[4][64];
    __shared__ __align__(16) float red[2][8][64];
    int b = blockIdx.x >> 1;
    int dbase = (blockIdx.x & 1) * 64;
    int tid = threadIdx.x;
    int dgi = tid & 31, mg = tid >> 5;
    int d0 = dbase + dgi * 2;

    for (int t = tid; t < TT; t += 256) {
        int s = skill[b * TT + t];
        int aa = answer[b * TT + t];
        if (aa > 1) aa = 1;
        s_sk[t] = s;
        s_x[t] = s + NUM_C * aa;
    }

    float mv[7][2];
    #pragma unroll
    for (int i = 0; i < 7; i++) {
        int m = mg * 7 + i;
        if (m < MM) {
            float2 v = *(const float2*)&Mv0[m * DIM + d0];
            mv[i][0] = v.x; mv[i][1] = v.y;
        } else {
            mv[i][0] = 0.f; mv[i][1] = 0.f;
        }
    }
    __syncthreads();   // s_sk/s_x visible

    bool lp = tid < 184;
    // gather helper roles: tid<56 -> w, <120 -> e, <184 -> a
    // prologue: step0 direct to buf0; step1 -> pfA (slot0); step2 -> pfB (slot1)
    float pfA = 0.f, pfB = 0.f;
    if (lp) {
        float v0, v1, v2;
        if (tid < MP) {
            v0 = g_w[s_sk[0] * MP + tid];
            v1 = g_w[s_sk[1] * MP + tid];
            v2 = g_w[s_sk[2] * MP + tid];
            w_sh[0][tid] = v0;
        } else if (tid < 120) {
            int o = dbase + (tid - 56);
            v0 = g_ea[s_x[0] * 256 + o];
            v1 = g_ea[s_x[1] * 256 + o];
            v2 = g_ea[s_x[2] * 256 + o];
            e_sh[0][tid - 56] = v0;
        } else {
            int o = 128 + dbase + (tid - 120);
            v0 = g_ea[s_x[0] * 256 + o];
            v1 = g_ea[s_x[1] * 256 + o];
            v2 = g_ea[s_x[2] * 256 + o];
            a_sh[0][tid - 120] = v0;
        }
        pfA = v1; pfB = v2;
    }
    __syncthreads();

    for (int t = 0; t < TT; t++) {
        int cur = t & 3;
        // ---- compute step t (recurrence critical path) ----
        float2 e2 = *(const float2*)&e_sh[cur][dgi * 2];
        float2 a2 = *(const float2*)&a_sh[cur][dgi * 2];
        float acc0 = 0.f, acc1 = 0.f;
        #pragma unroll
        for (int i = 0; i < 7; i++) {
            float wm = w_sh[cur][mg * 7 + i];
            acc0 = fmaf(wm, mv[i][0], acc0);          // read uses PRE-update Mv
            acc1 = fmaf(wm, mv[i][1], acc1);
            mv[i][0] = fmaf(wm, fmaf(-e2.x, mv[i][0], a2.x), mv[i][0]);
            mv[i][1] = fmaf(wm, fmaf(-e2.y, mv[i][1], a2.y), mv[i][1]);
        }
        *(float2*)&red[t & 1][mg][dgi * 2] = make_float2(acc0, acc1);
        // ---- STS: data for step t+1 (loaded at t-2) ----
        if (lp) {
            float pv = (t & 1) ? pfB : pfA;
            int nb = (t + 1) & 3;
            if (tid < MP)       w_sh[nb][tid] = pv;
            else if (tid < 120) e_sh[nb][tid - 56] = pv;
            else                a_sh[nb][tid - 120] = pv;
        }
        // ---- LDG: fetch step t+3 into the slot just freed ----
        if (lp && t + 3 < TT) {
            float nv;
            if (tid < MP)       nv = g_w[s_sk[t + 3] * MP + tid];
            else if (tid < 120) nv = g_ea[s_x[t + 3] * 256 + dbase + (tid - 56)];
            else                nv = g_ea[s_x[t + 3] * 256 + 128 + dbase + (tid - 120)];
            if (t & 1) pfB = nv; else pfA = nv;
        }
        // ---- deferred reduction of step t-1 ----
        if (t > 0 && tid < 64) {
            float s = 0.f;
            #pragma unroll
            for (int i = 0; i < 8; i++) s += red[(t - 1) & 1][i][tid];
            g_reads[(b * TT + t - 1) * DIM + dbase + tid] = s;
        }
        __syncthreads();
    }
    if (tid < 64) {
        float s = 0.f;
        #pragma unroll
        for (int i = 0; i < 8; i++) s += red[(TT - 1) & 1][i][tid];
        g_reads[(b * TT + TT - 1) * DIM + dbase + tid] = s;
    }
}

// ---------------- f = tanh(reads@fWa + kf[skill]) then gathered pred -----
__global__ void k_fpred(const int* __restrict__ skill, const float* __restrict__ p_W,
                        const float* __restrict__ p_b, float* __restrict__ out) {
    __shared__ float Xs[64][130];                 // reads tile; later reused for f
    __shared__ __align__(16) float Ws[16][DIM];
    __shared__ int s_kf[64], s_nx[64], roff[64];
    int row0 = blockIdx.x * 64;
    int tid = threadIdx.x;
    if (tid < 64) {
        int r = row0 + tid;
        int b = r / 199;
        int t = r - b * 199;
        s_kf[tid] = skill[b * TT + t];
        s_nx[tid] = skill[b * TT + t + 1];
        roff[tid] = (b * TT + t) * DIM;
    }
    __syncthreads();
    for (int i = tid; i < 64 * DIM; i += 256) {
        int rr = i >> 7, k = i & 127;
        Xs[rr][k] = g_reads[roff[rr] + k];
    }
    int tx = tid & 15, ty = tid >> 4;   // col = tx*8, rows = ty*4..
    float acc[4][8];
    #pragma unroll
    for (int u = 0; u < 4; u++)
        #pragma unroll
        for (int v = 0; v < 8; v++) acc[u][v] = 0.f;
    for (int kc = 0; kc < DIM; kc += 16) {
        __syncthreads();
        for (int i = tid; i < 16 * DIM; i += 256)
            Ws[i >> 7][i & 127] = g_fWat[(kc + (i >> 7)) * DIM + (i & 127)];
        __syncthreads();
        #pragma unroll
        for (int kk = 0; kk < 16; kk++) {
            float xv[4];
            #pragma unroll
            for (int u = 0; u < 4; u++) xv[u] = Xs[ty * 4 + u][kc + kk];
            float4 w0 = *(const float4*)&Ws[kk][tx * 8];
            float4 w1 = *(const float4*)&Ws[kk][tx * 8 + 4];
            #pragma unroll
            for (int u = 0; u < 4; u++) {
                acc[u][0] = fmaf(xv[u], w0.x, acc[u][0]);
                acc[u][1] = fmaf(xv[u], w0.y, acc[u][1]);
                acc[u][2] = fmaf(xv[u], w0.z, acc[u][2]);
                acc[u][3] = fmaf(xv[u], w0.w, acc[u][3]);
                acc[u][4] = fmaf(xv[u], w1.x, acc[u][4]);
                acc[u][5] = fmaf(xv[u], w1.y, acc[u][5]);
                acc[u][6] = fmaf(xv[u], w1.z, acc[u][6]);
                acc[u][7] = fmaf(xv[u], w1.w, acc[u][7]);
            }
        }
    }
    __syncthreads();   // everyone done reading Xs -> overwrite with f
    int col = tx * 8;
    #pragma unroll
    for (int u = 0; u < 4; u++) {
        int row = ty * 4 + u;
        int sc = s_kf[row];
        float4 k0 = *(const float4*)&g_kf[sc * DIM + col];
        float4 k1 = *(const float4*)&g_kf[sc * DIM + col + 4];
        Xs[row][col + 0] = tanhf(acc[u][0] + k0.x);
        Xs[row][col + 1] = tanhf(acc[u][1] + k0.y);
        Xs[row][col + 2] = tanhf(acc[u][2] + k0.z);
        Xs[row][col + 3] = tanhf(acc[u][3] + k0.w);
        Xs[row][col + 4] = tanhf(acc[u][4] + k1.x);
        Xs[row][col + 5] = tanhf(acc[u][5] + k1.y);
        Xs[row][col + 6] = tanhf(acc[u][6] + k1.z);
        Xs[row][col + 7] = tanhf(acc[u][7] + k1.w);
    }
    __syncthreads();
    // pred: one warp handles 8 rows; full-warp dot of f(row) with p_W[idx]
    int wid = tid >> 5, lane = tid & 31;
    for (int rr = wid * 8; rr < wid * 8 + 8; rr++) {
        int ns = s_nx[rr];
        int idx = (ns < NUM_C) ? ns : (NUM_C - 1);
        const float* pw = p_W + idx * DIM;
        float a = 0.f;
        #pragma unroll
        for (int q = 0; q < 4; q++) a = fmaf(Xs[rr][lane + 32 * q], pw[lane + 32 * q], a);
        #pragma unroll
        for (int off = 16; off; off >>= 1) a += __shfl_xor_sync(~0u, a, off);
        if (lane == 0) {
            float pr = sigmoidf_(a + p_b[idx]);
            out[row0 + rr] = (ns < NUM_C) ? pr : 0.f;
        }
    }
}

// ---------------- launch ---------------------------------------------------
extern "C" void kernel_launch(void* const* d_in, const int* in_sizes, int n_in,
                              void* d_out, int out_size) {
    const int*   skill  = (const int*)d_in[0];
    const int*   answer = (const int*)d_in[1];
    const float* k_emb  = (const float*)d_in[2];
    const float* v_emb  = (const float*)d_in[3];
    const float* Mk     = (const float*)d_in[4];
    const float* Mv0    = (const float*)d_in[5];
    const float* f_W    = (const float*)d_in[6];
    const float* f_b    = (const float*)d_in[7];
    const float* p_W    = (const float*)d_in[8];
    const float* p_b    = (const float*)d_in[9];
    const float* e_W    = (const float*)d_in[10];
    const float* e_b    = (const float*)d_in[11];
    const float* a_W    = (const float*)d_in[12];
    const float* a_b    = (const float*)d_in[13];
    float* out = (float*)d_out;

    k_tables<<<321, 256>>>(k_emb, Mk, v_emb, e_b, a_b, f_W, f_b, e_W, a_W);
    k_scan  <<<128, 256>>>(skill, answer, Mv0);
    k_fpred <<<199, 256>>>(skill, p_W, p_b, out);
}